// round 8
// baseline (speedup 1.0000x reference)
#include <cuda_runtime.h>
#include <math.h>
#include <stdint.h>

typedef unsigned long long ull;

// Problem constants
#define BATCH 512
#define C 3
#define NIMG 128
#define LNUM 3
#define H_ELEMS (BATCH * C * NIMG * NIMG)   // 25165824
#define TILES 32                            // 4 x-tiles (32 wide) x 8 y-tiles (16 tall)
#define LN2F 0.69314718055994531f
#define ECB_BLKS 192                        // 192*256 = 49152 = 3*128*128 pixels

// ---------------- device scratch (no allocations allowed) ----------------
// channel-interleaved epilogue table: [l][y][x][8] = {e0,b0,e1,b1,e2,b2,0,0}
__device__ __align__(16) float g_ecb2[LNUM * NIMG * NIMG * 8];
__device__ __align__(16) ull   g_Wpk[LNUM * 90];   // packed dup weights [l][(in*3+o)*10+tap]
__device__ __align__(16) float g_aux[LNUM * 12];   // B[3], alpha[3], ln2/alpha[3], pad
__device__ float g_cls_part[ECB_BLKS];
__device__ float g_kld_part[LNUM * 64];
__device__ float g_scratch[BATCH * TILES];

// Constant bank: weight pairs + per-layer aux (uniform pipe, no L1TEX, no GPRs)
__constant__ ull   c_W[LNUM * 90];
__constant__ float c_aux[LNUM * 12];

// ---------------- packed f32x2 helpers ----------------
__device__ __forceinline__ ull pk(float lo, float hi) {
    ull r; asm("mov.b64 %0,{%1,%2};" : "=l"(r) : "f"(lo), "f"(hi)); return r;
}
__device__ __forceinline__ void upk(ull p, float& lo, float& hi) {
    asm("mov.b64 {%0,%1},%2;" : "=f"(lo), "=f"(hi) : "l"(p));
}
__device__ __forceinline__ ull f2fma(ull a, ull b, ull c) {
    ull d; asm("fma.rn.f32x2 %0,%1,%2,%3;" : "=l"(d) : "l"(a), "l"(b), "l"(c)); return d;
}
// middle pair {hi(a), lo(b)}
__device__ __forceinline__ ull mkmid(ull a, ull b) {
    float alo, ahi, blo, bhi;
    asm("mov.b64 {%0,%1},%2;" : "=f"(alo), "=f"(ahi) : "l"(a));
    asm("mov.b64 {%0,%1},%2;" : "=f"(blo), "=f"(bhi) : "l"(b));
    ull m; asm("mov.b64 %0,{%1,%2};" : "=l"(m) : "f"(ahi), "f"(blo));
    return m;
}

// =========================================================================
// P1: build channel-interleaved {exp(cls), bias} table + partial cls sums.
// One thread per (layer, y, x) pixel handles all 3 channels.
// =========================================================================
__global__ void prep_ecb(const float* __restrict__ cls, const float* __restrict__ cbias) {
    __shared__ float sred[256];
    int p = blockIdx.x * 256 + threadIdx.x;   // < 49152
    int l = p >> 14;                          // /16384
    int yx = p & 16383;
    float v0 = cls[(l * 3 + 0) * 16384 + yx];
    float v1 = cls[(l * 3 + 1) * 16384 + yx];
    float v2 = cls[(l * 3 + 2) * 16384 + yx];
    float* d = g_ecb2 + (size_t)p * 8;
    d[0] = expf(v0); d[1] = cbias[(l * 3 + 0) * 16384 + yx];
    d[2] = expf(v1); d[3] = cbias[(l * 3 + 1) * 16384 + yx];
    d[4] = expf(v2); d[5] = cbias[(l * 3 + 2) * 16384 + yx];
    d[6] = 0.f; d[7] = 0.f;
    sred[threadIdx.x] = v0 + v1 + v2;
    __syncthreads();
    for (int s = 128; s > 0; s >>= 1) {
        if (threadIdx.x < s) sred[threadIdx.x] += sred[threadIdx.x + s];
        __syncthreads();
    }
    if (threadIdx.x == 0) g_cls_part[blockIdx.x] = sred[0];
}

// =========================================================================
// P2: fold actnorm into conv weights (packed dup ull), alpha tables
// =========================================================================
__global__ void prep_w(const float* __restrict__ K, const float* __restrict__ als,
                       const float* __restrict__ ab, const float* __restrict__ sla) {
    int t = threadIdx.x;
    for (int i = t; i < LNUM * 90; i += 256) {
        int l = i / 90, r = i % 90;
        int in = r / 30, r2 = r % 30;
        int o = r2 / 10, tap = r2 % 10;
        float val = 0.f;
        if (tap < 9) {
            float a = expf(als[l * 3 + in]);
            val = K[((l * 3 + o) * 3 + in) * 9 + tap] * a;
        }
        g_Wpk[i] = pk(val, val);
    }
    for (int i = t; i < LNUM * 12; i += 256) {
        int l = i / 12, j = i % 12;
        float val = 0.f;
        if (j < 3) {
            float s = 0.f;
            for (int in = 0; in < 3; in++) {
                float ks = 0.f;
                for (int tap = 0; tap < 9; tap++)
                    ks += K[((l * 3 + j) * 3 + in) * 9 + tap];
                s += ab[l * 3 + in] * ks;
            }
            val = s;
        } else if (j < 6) {
            val = expf(sla[l * 3 + (j - 3)]);
        } else if (j < 9) {
            val = LN2F / expf(sla[l * 3 + (j - 6)]);   // ln2/alpha
        }
        g_aux[i] = val;
    }
}

// =========================================================================
// P3: spectral log|det| of circular conv operator
// =========================================================================
__global__ void kld_kernel(const float* __restrict__ K) {
    __shared__ float2 tw[128];
    __shared__ float sK[LNUM * 81];
    __shared__ float sred[256];
    int tid = threadIdx.x;
    if (tid < 128) {
        double a = -2.0 * 3.14159265358979323846 * (double)tid / 128.0;
        double s, c; sincos(a, &s, &c);
        tw[tid] = make_float2((float)c, (float)s);
    }
    if (tid < LNUM * 81) sK[tid] = K[tid];
    __syncthreads();

    int point = blockIdx.x * 256 + tid;  // 64*256 = 16384
    int u = point >> 7, v = point & 127;

    float res[LNUM];
    #pragma unroll
    for (int l = 0; l < LNUM; l++) {
        float er[9], ei[9];
        #pragma unroll
        for (int p = 0; p < 3; p++)
            #pragma unroll
            for (int q = 0; q < 3; q++) {
                int m = (u * p + v * q) & 127;
                float2 t = tw[m];
                er[p * 3 + q] = t.x; ei[p * 3 + q] = t.y;
            }
        float mr[3][3], mi[3][3];
        #pragma unroll
        for (int a = 0; a < 3; a++)
            #pragma unroll
            for (int b = 0; b < 3; b++) {
                float rr = 0.f, ri = 0.f;
                #pragma unroll
                for (int t = 0; t < 9; t++) {
                    float kk = sK[l * 81 + (a * 3 + b) * 9 + t];
                    rr += kk * er[t]; ri += kk * ei[t];
                }
                mr[a][b] = rr; mi[a][b] = ri;
            }
        float c0r = (mr[1][1]*mr[2][2] - mi[1][1]*mi[2][2]) - (mr[1][2]*mr[2][1] - mi[1][2]*mi[2][1]);
        float c0i = (mr[1][1]*mi[2][2] + mi[1][1]*mr[2][2]) - (mr[1][2]*mi[2][1] + mi[1][2]*mr[2][1]);
        float c1r = (mr[1][0]*mr[2][2] - mi[1][0]*mi[2][2]) - (mr[1][2]*mr[2][0] - mi[1][2]*mi[2][0]);
        float c1i = (mr[1][0]*mi[2][2] + mi[1][0]*mr[2][2]) - (mr[1][2]*mi[2][0] + mi[1][2]*mr[2][0]);
        float c2r = (mr[1][0]*mr[2][1] - mi[1][0]*mi[2][1]) - (mr[1][1]*mr[2][0] - mi[1][1]*mi[2][0]);
        float c2i = (mr[1][0]*mi[2][1] + mi[1][0]*mr[2][1]) - (mr[1][1]*mi[2][0] + mi[1][1]*mr[2][0]);
        float dr = (mr[0][0]*c0r - mi[0][0]*c0i) - (mr[0][1]*c1r - mi[0][1]*c1i) + (mr[0][2]*c2r - mi[0][2]*c2i);
        float di = (mr[0][0]*c0i + mi[0][0]*c0r) - (mr[0][1]*c1i + mi[0][1]*c1r) + (mr[0][2]*c2i + mi[0][2]*c2r);
        res[l] = 0.5f * logf(dr * dr + di * di);
    }

    for (int l = 0; l < LNUM; l++) {
        sred[tid] = res[l];
        __syncthreads();
        for (int s = 128; s > 0; s >>= 1) {
            if (tid < s) sred[tid] += sred[tid + s];
            __syncthreads();
        }
        if (tid == 0) g_kld_part[l * 64 + blockIdx.x] = sred[0];
        __syncthreads();
    }
}

// =========================================================================
// One 2x2 quad of one stage. Weights + aux from constant bank.
// =========================================================================
template <int QW, bool LAST, int OFF, int LAYER>
__device__ __forceinline__ float do_quad(int q,
                                         const float* __restrict__ sin_, int pin,
                                         float* __restrict__ sout, int pout,
                                         float* __restrict__ gout,
                                         const float* __restrict__ ecb2,
                                         int ty0, int tx0) {
    int qy = q / QW, qx = q - qy * QW;
    int py = qy * 2, px = qx * 2;

    ull acc2[2][3];
    #pragma unroll
    for (int o = 0; o < 3; o++) {
        float B = c_aux[LAYER * 12 + o];
        acc2[0][o] = pk(B, B);
        acc2[1][o] = acc2[0][o];
    }

    #pragma unroll
    for (int in = 0; in < 3; in++) {
        const float* bp = sin_ + in * pin + py * 40 + px;
        ull A[4], Bv[4], M[4];
        #pragma unroll
        for (int r = 0; r < 4; r++) {
            A[r]  = *(const ull*)(bp + r * 40);
            Bv[r] = *(const ull*)(bp + r * 40 + 2);
            M[r]  = mkmid(A[r], Bv[r]);
        }
        #pragma unroll
        for (int o = 0; o < 3; o++) {
            #pragma unroll
            for (int ty = 0; ty < 3; ty++) {
                ull w0 = c_W[LAYER * 90 + (in * 3 + o) * 10 + ty * 3 + 0];
                ull w1 = c_W[LAYER * 90 + (in * 3 + o) * 10 + ty * 3 + 1];
                ull w2 = c_W[LAYER * 90 + (in * 3 + o) * 10 + ty * 3 + 2];
                acc2[0][o] = f2fma(w0, A[ty],      acc2[0][o]);
                acc2[0][o] = f2fma(w1, M[ty],      acc2[0][o]);
                acc2[0][o] = f2fma(w2, Bv[ty],     acc2[0][o]);
                acc2[1][o] = f2fma(w0, A[ty + 1],  acc2[1][o]);
                acc2[1][o] = f2fma(w1, M[ty + 1],  acc2[1][o]);
                acc2[1][o] = f2fma(w2, Bv[ty + 1], acc2[1][o]);
            }
        }
    }

    // ---- epilogue: channel-interleaved table, 32B/pixel, always aligned ----
    int xl0 = px - OFF, yl0 = py - OFF;
    int gy0 = (ty0 + yl0) & 127;
    int gy1 = (ty0 + yl0 + 1) & 127;
    int gx0 = (tx0 + xl0) & 127;
    int gx1 = (tx0 + xl0 + 1) & 127;

    // 8 loads: {ch0,ch1} via float4, ch2 via float2, for 2 rows x 2 cols
    const float* r0c0 = ecb2 + ((gy0 << 7) + gx0) * 8;
    const float* r0c1 = ecb2 + ((gy0 << 7) + gx1) * 8;
    const float* r1c0 = ecb2 + ((gy1 << 7) + gx0) * 8;
    const float* r1c1 = ecb2 + ((gy1 << 7) + gx1) * 8;
    float4 Qa[2][2]; float2 Qb[2][2];
    Qa[0][0] = *(const float4*)r0c0;  Qb[0][0] = *(const float2*)(r0c0 + 4);
    Qa[0][1] = *(const float4*)r0c1;  Qb[0][1] = *(const float2*)(r0c1 + 4);
    Qa[1][0] = *(const float4*)r1c0;  Qb[1][0] = *(const float2*)(r1c0 + 4);
    Qa[1][1] = *(const float4*)r1c1;  Qb[1][1] = *(const float2*)(r1c1 + 4);

    float lg2sum = 0.f;
    #pragma unroll
    for (int R = 0; R < 2; R++) {
        int yloc = py + R - OFF;
        int gy = R ? gy1 : gy0;
        #pragma unroll
        for (int o = 0; o < 3; o++) {
            float al   = c_aux[LAYER * 12 + 3 + o];
            float ial2 = c_aux[LAYER * 12 + 6 + o];
            float c0, c1; upk(acc2[R][o], c0, c1);
            float e0, b0, e1, b1;
            if (o == 0)      { e0 = Qa[R][0].x; b0 = Qa[R][0].y; e1 = Qa[R][1].x; b1 = Qa[R][1].y; }
            else if (o == 1) { e0 = Qa[R][0].z; b0 = Qa[R][0].w; e1 = Qa[R][1].z; b1 = Qa[R][1].w; }
            else             { e0 = Qb[R][0].x; b0 = Qb[R][0].y; e1 = Qb[R][1].x; b1 = Qb[R][1].y; }
            float u0 = fmaf(e0, c0, b0);
            float u1 = fmaf(e1, c1, b1);
            float g0 = __log2f(fmaf(al, fabsf(u0), 1.0f));   // lg2(1 + a|u|)
            float g1 = __log2f(fmaf(al, fabsf(u1), 1.0f));
            float h0 = copysignf(ial2 * g0, u0);             // (ln2/a)*lg2 = log1p/a
            float h1 = copysignf(ial2 * g1, u1);
            if (LAST || ((unsigned)yloc < 16u && (unsigned)xl0 < 32u))       lg2sum += g0;
            if (LAST || ((unsigned)yloc < 16u && (unsigned)(xl0 + 1) < 32u)) lg2sum += g1;
            if (!LAST) {
                *(ull*)&sout[o * pout + (py + R) * 40 + px] = pk(h0, h1);
            } else {
                *(float2*)(gout + ((size_t)o * NIMG + gy) * NIMG + (tx0 + px)) =
                    make_float2(h0, h1);
            }
        }
    }
    return lg2sum;
}

// =========================================================================
// One stage: quad loop has exactly <=2 iterations; unrolled explicitly.
// =========================================================================
template <int DH_ROWS, int DW, bool LAST, int OFF, int LAYER>
__device__ __forceinline__ float stage_p(const float* __restrict__ sin_, int pin,
                                         float* __restrict__ sout, int pout,
                                         float* __restrict__ gout,
                                         int ty0, int tx0, int tid) {
    const float* __restrict__ ecb2 = g_ecb2 + (size_t)LAYER * (NIMG * NIMG * 8);
    constexpr int QH = DH_ROWS / 2;
    constexpr int QW = DW / 2;
    constexpr int NQ = QH * QW;   // 180 / 153 / 128

    float s = do_quad<QW, LAST, OFF, LAYER>(tid, sin_, pin, sout, pout, gout, ecb2, ty0, tx0);
    if constexpr (NQ > 128) {
        if (tid < NQ - 128)
            s += do_quad<QW, LAST, OFF, LAYER>(tid + 128, sin_, pin, sout, pout, gout, ecb2, ty0, tx0);
    }
    return s;
}

__global__ void __launch_bounds__(128, 7) flow_main(const float* __restrict__ x,
                                                    float* __restrict__ out) {
    const int tid = threadIdx.x;
    const int b = blockIdx.x;        // batch-major: consecutive blocks share tile -> ecb reuse
    const int tile = blockIdx.y;     // 0..31 : 4 x-tiles * 8 y-tiles
    const int tx0 = (tile & 3) * 32;
    const int ty0 = (tile >> 2) * 16;

    __shared__ __align__(16) float sA[3 * 22 * 40];
    __shared__ __align__(16) float sB[3 * 20 * 40];
    __shared__ float sred[128];

    // Load raw input tile (22 rows x 38 cols, wrap halo of 3)
    const float* __restrict__ xb = x + (size_t)b * (C * NIMG * NIMG);
    for (int i = tid; i < 3 * 22 * 38; i += 128) {
        int c = i / (22 * 38);
        int rem = i - c * (22 * 38);
        int r = rem / 38;
        int col = rem - r * 38;
        int gy = (ty0 + r - 3) & 127;
        int gx = (tx0 + col - 3) & 127;
        sA[c * (22 * 40) + r * 40 + col] = xb[(c * NIMG + gy) * NIMG + gx];
    }
    __syncthreads();

    float lg2acc = 0.f;
    lg2acc += stage_p<20, 36, false, 2, 0>(sA, 22 * 40, sB, 20 * 40, nullptr, ty0, tx0, tid);
    __syncthreads();
    lg2acc += stage_p<18, 34, false, 1, 1>(sB, 20 * 40, sA, 18 * 40, nullptr, ty0, tx0, tid);
    __syncthreads();
    lg2acc += stage_p<16, 32, true, 0, 2>(sA, 18 * 40, nullptr, 0,
                                          out + (size_t)b * (C * NIMG * NIMG), ty0, tx0, tid);

    sred[tid] = lg2acc;
    __syncthreads();
    for (int s = 64; s > 0; s >>= 1) {
        if (tid < s) sred[tid] += sred[tid + s];
        __syncthreads();
    }
    if (tid == 0) g_scratch[b * TILES + tile] = -LN2F * sred[0];
}

// =========================================================================
// F: per-batch logdet = scalar part + 32 tile partials (deterministic)
// =========================================================================
__global__ void final_ld(const float* __restrict__ als, float* __restrict__ out) {
    __shared__ float sred[256];
    int tid = threadIdx.x;
    float loc = 0.f;
    for (int i = tid; i < ECB_BLKS; i += 256) loc += g_cls_part[i];
    for (int i = tid; i < LNUM * 64; i += 256) loc += g_kld_part[i];
    sred[tid] = loc;
    __syncthreads();
    for (int s = 128; s > 0; s >>= 1) {
        if (tid < s) sred[tid] += sred[tid + s];
        __syncthreads();
    }
    if (tid == 0) {
        float s2 = 0.f;
        for (int i = 0; i < 9; i++) s2 += als[i];
        sred[0] = sred[0] + 16384.0f * s2;
    }
    __syncthreads();
    float scal = sred[0];
    int b = blockIdx.x * 256 + tid;
    if (b < BATCH) {
        float s = scal;
        #pragma unroll
        for (int t = 0; t < TILES; t++) s += g_scratch[b * TILES + t];
        out[H_ELEMS + b] = s;
    }
}

// =========================================================================
extern "C" void kernel_launch(void* const* d_in, const int* in_sizes, int n_in,
                              void* d_out, int out_size) {
    const float* x     = (const float*)d_in[0];
    const float* ab    = (const float*)d_in[1];
    const float* als   = (const float*)d_in[2];
    const float* K     = (const float*)d_in[3];
    const float* cbias = (const float*)d_in[4];
    const float* cls   = (const float*)d_in[5];
    const float* sla   = (const float*)d_in[6];
    float* out = (float*)d_out;

    prep_ecb<<<ECB_BLKS, 256>>>(cls, cbias);
    prep_w<<<1, 256>>>(K, als, ab, sla);
    kld_kernel<<<64, 256>>>(K);

    // Device->constant-bank copies (graph-capturable D2D memcpy nodes).
    void* wsrc = nullptr;
    cudaGetSymbolAddress(&wsrc, g_Wpk);
    cudaMemcpyToSymbolAsync(c_W, wsrc, sizeof(ull) * LNUM * 90, 0,
                            cudaMemcpyDeviceToDevice, 0);
    void* asrc = nullptr;
    cudaGetSymbolAddress(&asrc, g_aux);
    cudaMemcpyToSymbolAsync(c_aux, asrc, sizeof(float) * LNUM * 12, 0,
                            cudaMemcpyDeviceToDevice, 0);

    flow_main<<<dim3(BATCH, TILES), 128>>>(x, out);   // 4th kernel (ncu target)
    final_ld<<<2, 256>>>(als, out);
}

// round 10
// speedup vs baseline: 1.3935x; 1.3935x over previous
#include <cuda_runtime.h>
#include <math.h>
#include <stdint.h>

typedef unsigned long long ull;

// Problem constants
#define BATCH 512
#define C 3
#define NIMG 128
#define LNUM 3
#define H_ELEMS (BATCH * C * NIMG * NIMG)   // 25165824
#define TILES 32                            // 4 x-tiles (32 wide) x 8 y-tiles (16 tall)
#define LN2F 0.69314718055994531f
#define ECB_BLKS 192                        // 192*256 = 49152 = 3*128*128 pixels

// ---------------- device scratch (no allocations allowed) ----------------
// channel-interleaved epilogue table: [l][y][x][8] = {e0,b0,e1,b1,e2,b2,0,0}
__device__ __align__(16) float g_ecb2[LNUM * NIMG * NIMG * 8];
__device__ __align__(16) ull   g_Wpk[LNUM * 90];   // packed dup weights [l][(in*3+o)*10+tap]
__device__ __align__(16) float g_aux[LNUM * 12];   // B[3], alpha[3], ln2/alpha[3], pad
__device__ float g_cls_part[ECB_BLKS];
__device__ float g_kld_part[LNUM * 64];
__device__ float g_scratch[BATCH * TILES];

// Constant bank: weight pairs + per-layer aux (uniform/const path, no L1TEX)
__constant__ ull   c_W[LNUM * 90];
__constant__ float c_aux[LNUM * 12];

// ---------------- packed f32x2 helpers ----------------
__device__ __forceinline__ ull pk(float lo, float hi) {
    ull r; asm("mov.b64 %0,{%1,%2};" : "=l"(r) : "f"(lo), "f"(hi)); return r;
}
__device__ __forceinline__ void upk(ull p, float& lo, float& hi) {
    asm("mov.b64 {%0,%1},%2;" : "=f"(lo), "=f"(hi) : "l"(p));
}
__device__ __forceinline__ ull f2fma(ull a, ull b, ull c) {
    ull d; asm("fma.rn.f32x2 %0,%1,%2,%3;" : "=l"(d) : "l"(a), "l"(b), "l"(c)); return d;
}
// middle pair {hi(a), lo(b)}
__device__ __forceinline__ ull mkmid(ull a, ull b) {
    float alo, ahi, blo, bhi;
    asm("mov.b64 {%0,%1},%2;" : "=f"(alo), "=f"(ahi) : "l"(a));
    asm("mov.b64 {%0,%1},%2;" : "=f"(blo), "=f"(bhi) : "l"(b));
    ull m; asm("mov.b64 %0,{%1,%2};" : "=l"(m) : "f"(ahi), "f"(blo));
    return m;
}

// =========================================================================
// P1: build channel-interleaved {exp(cls), bias} table + partial cls sums.
// =========================================================================
__global__ void prep_ecb(const float* __restrict__ cls, const float* __restrict__ cbias) {
    __shared__ float sred[256];
    int p = blockIdx.x * 256 + threadIdx.x;   // < 49152
    int l = p >> 14;                          // /16384
    int yx = p & 16383;
    float v0 = cls[(l * 3 + 0) * 16384 + yx];
    float v1 = cls[(l * 3 + 1) * 16384 + yx];
    float v2 = cls[(l * 3 + 2) * 16384 + yx];
    float* d = g_ecb2 + (size_t)p * 8;
    d[0] = expf(v0); d[1] = cbias[(l * 3 + 0) * 16384 + yx];
    d[2] = expf(v1); d[3] = cbias[(l * 3 + 1) * 16384 + yx];
    d[4] = expf(v2); d[5] = cbias[(l * 3 + 2) * 16384 + yx];
    d[6] = 0.f; d[7] = 0.f;
    sred[threadIdx.x] = v0 + v1 + v2;
    __syncthreads();
    for (int s = 128; s > 0; s >>= 1) {
        if (threadIdx.x < s) sred[threadIdx.x] += sred[threadIdx.x + s];
        __syncthreads();
    }
    if (threadIdx.x == 0) g_cls_part[blockIdx.x] = sred[0];
}

// =========================================================================
// P2: fold actnorm into conv weights (packed dup ull), alpha tables
// =========================================================================
__global__ void prep_w(const float* __restrict__ K, const float* __restrict__ als,
                       const float* __restrict__ ab, const float* __restrict__ sla) {
    int t = threadIdx.x;
    for (int i = t; i < LNUM * 90; i += 256) {
        int l = i / 90, r = i % 90;
        int in = r / 30, r2 = r % 30;
        int o = r2 / 10, tap = r2 % 10;
        float val = 0.f;
        if (tap < 9) {
            float a = expf(als[l * 3 + in]);
            val = K[((l * 3 + o) * 3 + in) * 9 + tap] * a;
        }
        g_Wpk[i] = pk(val, val);
    }
    for (int i = t; i < LNUM * 12; i += 256) {
        int l = i / 12, j = i % 12;
        float val = 0.f;
        if (j < 3) {
            float s = 0.f;
            for (int in = 0; in < 3; in++) {
                float ks = 0.f;
                for (int tap = 0; tap < 9; tap++)
                    ks += K[((l * 3 + j) * 3 + in) * 9 + tap];
                s += ab[l * 3 + in] * ks;
            }
            val = s;
        } else if (j < 6) {
            val = expf(sla[l * 3 + (j - 3)]);
        } else if (j < 9) {
            val = LN2F / expf(sla[l * 3 + (j - 6)]);   // ln2/alpha
        }
        g_aux[i] = val;
    }
}

// =========================================================================
// P3: spectral log|det| of circular conv operator
// =========================================================================
__global__ void kld_kernel(const float* __restrict__ K) {
    __shared__ float2 tw[128];
    __shared__ float sK[LNUM * 81];
    __shared__ float sred[256];
    int tid = threadIdx.x;
    if (tid < 128) {
        double a = -2.0 * 3.14159265358979323846 * (double)tid / 128.0;
        double s, c; sincos(a, &s, &c);
        tw[tid] = make_float2((float)c, (float)s);
    }
    if (tid < LNUM * 81) sK[tid] = K[tid];
    __syncthreads();

    int point = blockIdx.x * 256 + tid;  // 64*256 = 16384
    int u = point >> 7, v = point & 127;

    float res[LNUM];
    #pragma unroll
    for (int l = 0; l < LNUM; l++) {
        float er[9], ei[9];
        #pragma unroll
        for (int p = 0; p < 3; p++)
            #pragma unroll
            for (int q = 0; q < 3; q++) {
                int m = (u * p + v * q) & 127;
                float2 t = tw[m];
                er[p * 3 + q] = t.x; ei[p * 3 + q] = t.y;
            }
        float mr[3][3], mi[3][3];
        #pragma unroll
        for (int a = 0; a < 3; a++)
            #pragma unroll
            for (int b = 0; b < 3; b++) {
                float rr = 0.f, ri = 0.f;
                #pragma unroll
                for (int t = 0; t < 9; t++) {
                    float kk = sK[l * 81 + (a * 3 + b) * 9 + t];
                    rr += kk * er[t]; ri += kk * ei[t];
                }
                mr[a][b] = rr; mi[a][b] = ri;
            }
        float c0r = (mr[1][1]*mr[2][2] - mi[1][1]*mi[2][2]) - (mr[1][2]*mr[2][1] - mi[1][2]*mi[2][1]);
        float c0i = (mr[1][1]*mi[2][2] + mi[1][1]*mr[2][2]) - (mr[1][2]*mi[2][1] + mi[1][2]*mr[2][1]);
        float c1r = (mr[1][0]*mr[2][2] - mi[1][0]*mi[2][2]) - (mr[1][2]*mr[2][0] - mi[1][2]*mi[2][0]);
        float c1i = (mr[1][0]*mi[2][2] + mi[1][0]*mr[2][2]) - (mr[1][2]*mi[2][0] + mi[1][2]*mr[2][0]);
        float c2r = (mr[1][0]*mr[2][1] - mi[1][0]*mi[2][1]) - (mr[1][1]*mr[2][0] - mi[1][1]*mi[2][0]);
        float c2i = (mr[1][0]*mi[2][1] + mi[1][0]*mr[2][1]) - (mr[1][1]*mi[2][0] + mi[1][1]*mr[2][0]);
        float dr = (mr[0][0]*c0r - mi[0][0]*c0i) - (mr[0][1]*c1r - mi[0][1]*c1i) + (mr[0][2]*c2r - mi[0][2]*c2i);
        float di = (mr[0][0]*c0i + mi[0][0]*c0r) - (mr[0][1]*c1i + mi[0][1]*c1r) + (mr[0][2]*c2i + mi[0][2]*c2r);
        res[l] = 0.5f * logf(dr * dr + di * di);
    }

    for (int l = 0; l < LNUM; l++) {
        sred[tid] = res[l];
        __syncthreads();
        for (int s = 128; s > 0; s >>= 1) {
            if (tid < s) sred[tid] += sred[tid + s];
            __syncthreads();
        }
        if (tid == 0) g_kld_part[l * 64 + blockIdx.x] = sred[0];
        __syncthreads();
    }
}

// =========================================================================
// One 2x2 quad of one stage. Weights + aux from constant bank.
// =========================================================================
template <int QW, bool LAST, int OFF, int LAYER>
__device__ __forceinline__ float do_quad(int q,
                                         const float* __restrict__ sin_, int pin,
                                         float* __restrict__ sout, int pout,
                                         float* __restrict__ gout,
                                         const float* __restrict__ ecb2,
                                         int ty0, int tx0) {
    int qy = q / QW, qx = q - qy * QW;
    int py = qy * 2, px = qx * 2;

    ull acc2[2][3];
    #pragma unroll
    for (int o = 0; o < 3; o++) {
        float B = c_aux[LAYER * 12 + o];
        acc2[0][o] = pk(B, B);
        acc2[1][o] = acc2[0][o];
    }

    #pragma unroll
    for (int in = 0; in < 3; in++) {
        const float* bp = sin_ + in * pin + py * 40 + px;
        ull A[4], Bv[4], M[4];
        #pragma unroll
        for (int r = 0; r < 4; r++) {
            A[r]  = *(const ull*)(bp + r * 40);
            Bv[r] = *(const ull*)(bp + r * 40 + 2);
            M[r]  = mkmid(A[r], Bv[r]);
        }
        #pragma unroll
        for (int o = 0; o < 3; o++) {
            #pragma unroll
            for (int ty = 0; ty < 3; ty++) {
                ull w0 = c_W[LAYER * 90 + (in * 3 + o) * 10 + ty * 3 + 0];
                ull w1 = c_W[LAYER * 90 + (in * 3 + o) * 10 + ty * 3 + 1];
                ull w2 = c_W[LAYER * 90 + (in * 3 + o) * 10 + ty * 3 + 2];
                acc2[0][o] = f2fma(w0, A[ty],      acc2[0][o]);
                acc2[0][o] = f2fma(w1, M[ty],      acc2[0][o]);
                acc2[0][o] = f2fma(w2, Bv[ty],     acc2[0][o]);
                acc2[1][o] = f2fma(w0, A[ty + 1],  acc2[1][o]);
                acc2[1][o] = f2fma(w1, M[ty + 1],  acc2[1][o]);
                acc2[1][o] = f2fma(w2, Bv[ty + 1], acc2[1][o]);
            }
        }
    }

    // ---- epilogue: channel-interleaved table, 32B/pixel, always aligned ----
    int xl0 = px - OFF, yl0 = py - OFF;
    int gy0 = (ty0 + yl0) & 127;
    int gy1 = (ty0 + yl0 + 1) & 127;
    int gx0 = (tx0 + xl0) & 127;
    int gx1 = (tx0 + xl0 + 1) & 127;

    const float* r0c0 = ecb2 + ((gy0 << 7) + gx0) * 8;
    const float* r0c1 = ecb2 + ((gy0 << 7) + gx1) * 8;
    const float* r1c0 = ecb2 + ((gy1 << 7) + gx0) * 8;
    const float* r1c1 = ecb2 + ((gy1 << 7) + gx1) * 8;

    float lg2sum = 0.f;
    #pragma unroll
    for (int R = 0; R < 2; R++) {
        int yloc = py + R - OFF;
        int gy = R ? gy1 : gy0;
        const float* pc0 = R ? r1c0 : r0c0;
        const float* pc1 = R ? r1c1 : r0c1;
        float4 Ea = *(const float4*)pc0;          // e0,b0,e1,b1 col0
        float2 Eb = *(const float2*)(pc0 + 4);    // e2,b2      col0
        float4 Fa = *(const float4*)pc1;          // col1
        float2 Fb = *(const float2*)(pc1 + 4);
        #pragma unroll
        for (int o = 0; o < 3; o++) {
            float al   = c_aux[LAYER * 12 + 3 + o];
            float ial2 = c_aux[LAYER * 12 + 6 + o];
            float c0, c1; upk(acc2[R][o], c0, c1);
            float e0, b0, e1, b1;
            if (o == 0)      { e0 = Ea.x; b0 = Ea.y; e1 = Fa.x; b1 = Fa.y; }
            else if (o == 1) { e0 = Ea.z; b0 = Ea.w; e1 = Fa.z; b1 = Fa.w; }
            else             { e0 = Eb.x; b0 = Eb.y; e1 = Fb.x; b1 = Fb.y; }
            float u0 = fmaf(e0, c0, b0);
            float u1 = fmaf(e1, c1, b1);
            float g0 = __log2f(fmaf(al, fabsf(u0), 1.0f));   // lg2(1 + a|u|)
            float g1 = __log2f(fmaf(al, fabsf(u1), 1.0f));
            float h0 = copysignf(ial2 * g0, u0);             // (ln2/a)*lg2 = log1p/a
            float h1 = copysignf(ial2 * g1, u1);
            if (LAST || ((unsigned)yloc < 16u && (unsigned)xl0 < 32u))       lg2sum += g0;
            if (LAST || ((unsigned)yloc < 16u && (unsigned)(xl0 + 1) < 32u)) lg2sum += g1;
            if (!LAST) {
                *(ull*)&sout[o * pout + (py + R) * 40 + px] = pk(h0, h1);
            } else {
                *(float2*)(gout + ((size_t)o * NIMG + gy) * NIMG + (tx0 + px)) =
                    make_float2(h0, h1);
            }
        }
    }
    return lg2sum;
}

// =========================================================================
// One stage: quad loop has exactly <=2 iterations; unrolled explicitly.
// =========================================================================
template <int DH_ROWS, int DW, bool LAST, int OFF, int LAYER>
__device__ __forceinline__ float stage_p(const float* __restrict__ sin_, int pin,
                                         float* __restrict__ sout, int pout,
                                         float* __restrict__ gout,
                                         int ty0, int tx0, int tid) {
    const float* __restrict__ ecb2 = g_ecb2 + (size_t)LAYER * (NIMG * NIMG * 8);
    constexpr int QH = DH_ROWS / 2;
    constexpr int QW = DW / 2;
    constexpr int NQ = QH * QW;   // 180 / 153 / 128

    float s = do_quad<QW, LAST, OFF, LAYER>(tid, sin_, pin, sout, pout, gout, ecb2, ty0, tx0);
    if constexpr (NQ > 128) {
        if (tid < NQ - 128)
            s += do_quad<QW, LAST, OFF, LAYER>(tid + 128, sin_, pin, sout, pout, gout, ecb2, ty0, tx0);
    }
    return s;
}

__global__ void __launch_bounds__(128, 6) flow_main(const float* __restrict__ x,
                                                    float* __restrict__ out) {
    const int tid = threadIdx.x;
    const int b = blockIdx.x;        // batch-major: consecutive blocks share tile -> ecb reuse
    const int tile = blockIdx.y;     // 0..31 : 4 x-tiles * 8 y-tiles
    const int tx0 = (tile & 3) * 32;
    const int ty0 = (tile >> 2) * 16;

    __shared__ __align__(16) float sA[3 * 22 * 40];
    __shared__ __align__(16) float sB[3 * 20 * 40];
    __shared__ float sred[128];

    // Load raw input tile (22 rows x 38 cols, wrap halo of 3)
    const float* __restrict__ xb = x + (size_t)b * (C * NIMG * NIMG);
    for (int i = tid; i < 3 * 22 * 38; i += 128) {
        int c = i / (22 * 38);
        int rem = i - c * (22 * 38);
        int r = rem / 38;
        int col = rem - r * 38;
        int gy = (ty0 + r - 3) & 127;
        int gx = (tx0 + col - 3) & 127;
        sA[c * (22 * 40) + r * 40 + col] = xb[(c * NIMG + gy) * NIMG + gx];
    }
    __syncthreads();

    float lg2acc = 0.f;
    lg2acc += stage_p<20, 36, false, 2, 0>(sA, 22 * 40, sB, 20 * 40, nullptr, ty0, tx0, tid);
    __syncthreads();
    lg2acc += stage_p<18, 34, false, 1, 1>(sB, 20 * 40, sA, 18 * 40, nullptr, ty0, tx0, tid);
    __syncthreads();
    lg2acc += stage_p<16, 32, true, 0, 2>(sA, 18 * 40, nullptr, 0,
                                          out + (size_t)b * (C * NIMG * NIMG), ty0, tx0, tid);

    sred[tid] = lg2acc;
    __syncthreads();
    for (int s = 64; s > 0; s >>= 1) {
        if (tid < s) sred[tid] += sred[tid + s];
        __syncthreads();
    }
    if (tid == 0) g_scratch[b * TILES + tile] = -LN2F * sred[0];
}

// =========================================================================
// F: per-batch logdet = scalar part + 32 tile partials (deterministic)
// =========================================================================
__global__ void final_ld(const float* __restrict__ als, float* __restrict__ out) {
    __shared__ float sred[256];
    int tid = threadIdx.x;
    float loc = 0.f;
    for (int i = tid; i < ECB_BLKS; i += 256) loc += g_cls_part[i];
    for (int i = tid; i < LNUM * 64; i += 256) loc += g_kld_part[i];
    sred[tid] = loc;
    __syncthreads();
    for (int s = 128; s > 0; s >>= 1) {
        if (tid < s) sred[tid] += sred[tid + s];
        __syncthreads();
    }
    if (tid == 0) {
        float s2 = 0.f;
        for (int i = 0; i < 9; i++) s2 += als[i];
        sred[0] = sred[0] + 16384.0f * s2;
    }
    __syncthreads();
    float scal = sred[0];
    int b = blockIdx.x * 256 + tid;
    if (b < BATCH) {
        float s = scal;
        #pragma unroll
        for (int t = 0; t < TILES; t++) s += g_scratch[b * TILES + t];
        out[H_ELEMS + b] = s;
    }
}

// =========================================================================
extern "C" void kernel_launch(void* const* d_in, const int* in_sizes, int n_in,
                              void* d_out, int out_size) {
    const float* x     = (const float*)d_in[0];
    const float* ab    = (const float*)d_in[1];
    const float* als   = (const float*)d_in[2];
    const float* K     = (const float*)d_in[3];
    const float* cbias = (const float*)d_in[4];
    const float* cls   = (const float*)d_in[5];
    const float* sla   = (const float*)d_in[6];
    float* out = (float*)d_out;

    prep_ecb<<<ECB_BLKS, 256>>>(cls, cbias);
    prep_w<<<1, 256>>>(K, als, ab, sla);
    kld_kernel<<<64, 256>>>(K);

    // Device->constant-bank copies (graph-capturable D2D memcpy nodes).
    void* wsrc = nullptr;
    cudaGetSymbolAddress(&wsrc, g_Wpk);
    cudaMemcpyToSymbolAsync(c_W, wsrc, sizeof(ull) * LNUM * 90, 0,
                            cudaMemcpyDeviceToDevice, 0);
    void* asrc = nullptr;
    cudaGetSymbolAddress(&asrc, g_aux);
    cudaMemcpyToSymbolAsync(c_aux, asrc, sizeof(float) * LNUM * 12, 0,
                            cudaMemcpyDeviceToDevice, 0);

    flow_main<<<dim3(BATCH, TILES), 128>>>(x, out);   // 4th kernel (ncu target)
    final_ld<<<2, 256>>>(als, out);
}

// round 13
// speedup vs baseline: 1.5210x; 1.0916x over previous
#include <cuda_runtime.h>
#include <math.h>
#include <stdint.h>

typedef unsigned long long ull;

// Problem constants
#define BATCH 512
#define C 3
#define NIMG 128
#define LNUM 3
#define H_ELEMS (BATCH * C * NIMG * NIMG)   // 25165824
#define TILES 32                            // 4 x-tiles (32 wide) x 8 y-tiles (16 tall)
#define LN2F 0.69314718055994531f

// ---------------- device scratch (no allocations allowed) ----------------
__device__ __align__(16) float g_ecb[LNUM * C * NIMG * NIMG * 2]; // {exp(cls), bias} dense 16B/px
__device__ __align__(16) ull   g_Wpk[LNUM * 90];   // packed dup weights [l][(in*3+o)*10+tap]
__device__ __align__(16) float g_aux[LNUM * 12];   // B[3], alpha[3], ln2/alpha[3], pad
__device__ float g_cls_part[576];
__device__ float g_kld_part[LNUM * 64];
__device__ float g_scratch[BATCH * TILES];

// Constant bank: weight pairs + per-layer aux (uniform/const path, no L1TEX)
__constant__ ull   c_W[LNUM * 90];
__constant__ float c_aux[LNUM * 12];

// ---------------- packed f32x2 helpers ----------------
__device__ __forceinline__ ull pk(float lo, float hi) {
    ull r; asm("mov.b64 %0,{%1,%2};" : "=l"(r) : "f"(lo), "f"(hi)); return r;
}
__device__ __forceinline__ void upk(ull p, float& lo, float& hi) {
    asm("mov.b64 {%0,%1},%2;" : "=f"(lo), "=f"(hi) : "l"(p));
}
__device__ __forceinline__ ull f2fma(ull a, ull b, ull c) {
    ull d; asm("fma.rn.f32x2 %0,%1,%2,%3;" : "=l"(d) : "l"(a), "l"(b), "l"(c)); return d;
}
// middle pair {hi(a), lo(b)}
__device__ __forceinline__ ull mkmid(ull a, ull b) {
    float alo, ahi, blo, bhi;
    asm("mov.b64 {%0,%1},%2;" : "=f"(alo), "=f"(ahi) : "l"(a));
    asm("mov.b64 {%0,%1},%2;" : "=f"(blo), "=f"(bhi) : "l"(b));
    ull m; asm("mov.b64 %0,{%1,%2};" : "=l"(m) : "f"(ahi), "f"(blo));
    return m;
}

// =========================================================================
// P1: exp(conv_log_scale) interleaved with conv_bias + partial sums of cls
// =========================================================================
__global__ void prep_ecb(const float* __restrict__ cls, const float* __restrict__ cbias) {
    __shared__ float sred[256];
    int idx = blockIdx.x * 256 + threadIdx.x;   // 576*256 = 147456 exactly
    float v = cls[idx];
    g_ecb[2 * idx]     = expf(v);
    g_ecb[2 * idx + 1] = cbias[idx];
    sred[threadIdx.x] = v;
    __syncthreads();
    for (int s = 128; s > 0; s >>= 1) {
        if (threadIdx.x < s) sred[threadIdx.x] += sred[threadIdx.x + s];
        __syncthreads();
    }
    if (threadIdx.x == 0) g_cls_part[blockIdx.x] = sred[0];
}

// =========================================================================
// P2: fold actnorm into conv weights (packed dup ull), alpha tables
// =========================================================================
__global__ void prep_w(const float* __restrict__ K, const float* __restrict__ als,
                       const float* __restrict__ ab, const float* __restrict__ sla) {
    int t = threadIdx.x;
    for (int i = t; i < LNUM * 90; i += 256) {
        int l = i / 90, r = i % 90;
        int in = r / 30, r2 = r % 30;
        int o = r2 / 10, tap = r2 % 10;
        float val = 0.f;
        if (tap < 9) {
            float a = expf(als[l * 3 + in]);
            val = K[((l * 3 + o) * 3 + in) * 9 + tap] * a;
        }
        g_Wpk[i] = pk(val, val);
    }
    for (int i = t; i < LNUM * 12; i += 256) {
        int l = i / 12, j = i % 12;
        float val = 0.f;
        if (j < 3) {
            float s = 0.f;
            for (int in = 0; in < 3; in++) {
                float ks = 0.f;
                for (int tap = 0; tap < 9; tap++)
                    ks += K[((l * 3 + j) * 3 + in) * 9 + tap];
                s += ab[l * 3 + in] * ks;
            }
            val = s;
        } else if (j < 6) {
            val = expf(sla[l * 3 + (j - 3)]);
        } else if (j < 9) {
            val = LN2F / expf(sla[l * 3 + (j - 6)]);   // ln2/alpha
        }
        g_aux[i] = val;
    }
}

// =========================================================================
// P3: spectral log|det| of circular conv operator
// =========================================================================
__global__ void kld_kernel(const float* __restrict__ K) {
    __shared__ float2 tw[128];
    __shared__ float sK[LNUM * 81];
    __shared__ float sred[256];
    int tid = threadIdx.x;
    if (tid < 128) {
        double a = -2.0 * 3.14159265358979323846 * (double)tid / 128.0;
        double s, c; sincos(a, &s, &c);
        tw[tid] = make_float2((float)c, (float)s);
    }
    if (tid < LNUM * 81) sK[tid] = K[tid];
    __syncthreads();

    int point = blockIdx.x * 256 + tid;  // 64*256 = 16384
    int u = point >> 7, v = point & 127;

    float res[LNUM];
    #pragma unroll
    for (int l = 0; l < LNUM; l++) {
        float er[9], ei[9];
        #pragma unroll
        for (int p = 0; p < 3; p++)
            #pragma unroll
            for (int q = 0; q < 3; q++) {
                int m = (u * p + v * q) & 127;
                float2 t = tw[m];
                er[p * 3 + q] = t.x; ei[p * 3 + q] = t.y;
            }
        float mr[3][3], mi[3][3];
        #pragma unroll
        for (int a = 0; a < 3; a++)
            #pragma unroll
            for (int b = 0; b < 3; b++) {
                float rr = 0.f, ri = 0.f;
                #pragma unroll
                for (int t = 0; t < 9; t++) {
                    float kk = sK[l * 81 + (a * 3 + b) * 9 + t];
                    rr += kk * er[t]; ri += kk * ei[t];
                }
                mr[a][b] = rr; mi[a][b] = ri;
            }
        float c0r = (mr[1][1]*mr[2][2] - mi[1][1]*mi[2][2]) - (mr[1][2]*mr[2][1] - mi[1][2]*mi[2][1]);
        float c0i = (mr[1][1]*mi[2][2] + mi[1][1]*mr[2][2]) - (mr[1][2]*mi[2][1] + mi[1][2]*mr[2][1]);
        float c1r = (mr[1][0]*mr[2][2] - mi[1][0]*mi[2][2]) - (mr[1][2]*mr[2][0] - mi[1][2]*mi[2][0]);
        float c1i = (mr[1][0]*mi[2][2] + mi[1][0]*mr[2][2]) - (mr[1][2]*mi[2][0] + mi[1][2]*mr[2][0]);
        float c2r = (mr[1][0]*mr[2][1] - mi[1][0]*mi[2][1]) - (mr[1][1]*mr[2][0] - mi[1][1]*mi[2][0]);
        float c2i = (mr[1][0]*mi[2][1] + mi[1][0]*mr[2][1]) - (mr[1][1]*mi[2][0] + mi[1][1]*mr[2][0]);
        float dr = (mr[0][0]*c0r - mi[0][0]*c0i) - (mr[0][1]*c1r - mi[0][1]*c1i) + (mr[0][2]*c2r - mi[0][2]*c2i);
        float di = (mr[0][0]*c0i + mi[0][0]*c0r) - (mr[0][1]*c1i + mi[0][1]*c1r) + (mr[0][2]*c2i + mi[0][2]*c2r);
        res[l] = 0.5f * logf(dr * dr + di * di);
    }

    for (int l = 0; l < LNUM; l++) {
        sred[tid] = res[l];
        __syncthreads();
        for (int s = 128; s > 0; s >>= 1) {
            if (tid < s) sred[tid] += sred[tid + s];
            __syncthreads();
        }
        if (tid == 0) g_kld_part[l * 64 + blockIdx.x] = sred[0];
        __syncthreads();
    }
}

// =========================================================================
// One 2x2 quad of one stage. Weights + aux from constant bank;
// epilogue = R7 proven form (dense 16B/px table, float2 loads).
// =========================================================================
template <int QW, bool LAST, int OFF, int LAYER>
__device__ __forceinline__ float do_quad(int q,
                                         const float* __restrict__ sin_, int pin,
                                         float* __restrict__ sout, int pout,
                                         float* __restrict__ gout,
                                         const float* __restrict__ ecb,
                                         int ty0, int tx0) {
    int qy = q / QW, qx = q - qy * QW;
    int py = qy * 2, px = qx * 2;

    ull acc2[2][3];
    #pragma unroll
    for (int o = 0; o < 3; o++) {
        float B = c_aux[LAYER * 12 + o];
        acc2[0][o] = pk(B, B);
        acc2[1][o] = acc2[0][o];
    }

    #pragma unroll
    for (int in = 0; in < 3; in++) {
        const float* bp = sin_ + in * pin + py * 40 + px;
        ull A[4], Bv[4], M[4];
        #pragma unroll
        for (int r = 0; r < 4; r++) {
            A[r]  = *(const ull*)(bp + r * 40);
            Bv[r] = *(const ull*)(bp + r * 40 + 2);
            M[r]  = mkmid(A[r], Bv[r]);
        }
        #pragma unroll
        for (int o = 0; o < 3; o++) {
            #pragma unroll
            for (int ty = 0; ty < 3; ty++) {
                ull w0 = c_W[LAYER * 90 + (in * 3 + o) * 10 + ty * 3 + 0];
                ull w1 = c_W[LAYER * 90 + (in * 3 + o) * 10 + ty * 3 + 1];
                ull w2 = c_W[LAYER * 90 + (in * 3 + o) * 10 + ty * 3 + 2];
                acc2[0][o] = f2fma(w0, A[ty],      acc2[0][o]);
                acc2[0][o] = f2fma(w1, M[ty],      acc2[0][o]);
                acc2[0][o] = f2fma(w2, Bv[ty],     acc2[0][o]);
                acc2[1][o] = f2fma(w0, A[ty + 1],  acc2[1][o]);
                acc2[1][o] = f2fma(w1, M[ty + 1],  acc2[1][o]);
                acc2[1][o] = f2fma(w2, Bv[ty + 1], acc2[1][o]);
            }
        }
    }

    // ---- epilogue (R7 form: dense table, scattered float2 loads) ----
    int xl0 = px - OFF, yl0 = py - OFF;
    int gy0 = (ty0 + yl0) & 127;
    int gy1 = (ty0 + yl0 + 1) & 127;
    int gx0 = (tx0 + xl0) & 127;
    int gx1 = (tx0 + xl0 + 1) & 127;

    float lg2sum = 0.f;
    #pragma unroll
    for (int R = 0; R < 2; R++) {
        int yloc = py + R - OFF;
        int gy = R ? gy1 : gy0;
        #pragma unroll
        for (int o = 0; o < 3; o++) {
            float al   = c_aux[LAYER * 12 + 3 + o];
            float ial2 = c_aux[LAYER * 12 + 6 + o];
            float c0, c1; upk(acc2[R][o], c0, c1);
            float2 e0 = *(const float2*)&ecb[((o * NIMG + gy) * NIMG + gx0) * 2];
            float2 e1 = *(const float2*)&ecb[((o * NIMG + gy) * NIMG + gx1) * 2];
            float u0 = fmaf(e0.x, c0, e0.y);
            float u1 = fmaf(e1.x, c1, e1.y);
            float g0 = __log2f(fmaf(al, fabsf(u0), 1.0f));   // lg2(1 + a|u|)
            float g1 = __log2f(fmaf(al, fabsf(u1), 1.0f));
            float h0 = copysignf(ial2 * g0, u0);             // (ln2/a)*lg2 = log1p/a
            float h1 = copysignf(ial2 * g1, u1);
            if (LAST || ((unsigned)yloc < 16u && (unsigned)xl0 < 32u))       lg2sum += g0;
            if (LAST || ((unsigned)yloc < 16u && (unsigned)(xl0 + 1) < 32u)) lg2sum += g1;
            if (!LAST) {
                *(ull*)&sout[o * pout + (py + R) * 40 + px] = pk(h0, h1);
            } else {
                *(float2*)(gout + ((size_t)o * NIMG + gy) * NIMG + (tx0 + px)) =
                    make_float2(h0, h1);
            }
        }
    }
    return lg2sum;
}

// =========================================================================
// One stage. Overflow quads (NQ-128) are rotated across warps per stage
// (HIGH_OVF: high tids / warps 2-3; else low tids / warp 0) to balance
// per-SMSP issue load: per-block warp quad-loads become (4,3,4,4)
// instead of (5,4,3,3).
// =========================================================================
template <int DH_ROWS, int DW, bool LAST, int OFF, int LAYER, bool HIGH_OVF>
__device__ __forceinline__ float stage_p(const float* __restrict__ sin_, int pin,
                                         float* __restrict__ sout, int pout,
                                         float* __restrict__ gout,
                                         int ty0, int tx0, int tid) {
    const float* __restrict__ ecb = g_ecb + LAYER * (C * NIMG * NIMG * 2);
    constexpr int QH = DH_ROWS / 2;
    constexpr int QW = DW / 2;
    constexpr int NQ = QH * QW;   // 180 / 153 / 128

    float s = do_quad<QW, LAST, OFF, LAYER>(tid, sin_, pin, sout, pout, gout, ecb, ty0, tx0);
    if constexpr (NQ > 128) {
        constexpr int V = NQ - 128;
        if constexpr (HIGH_OVF) {
            if (tid >= 128 - V)
                s += do_quad<QW, LAST, OFF, LAYER>(tid + V, sin_, pin, sout, pout, gout, ecb, ty0, tx0);
        } else {
            if (tid < V)
                s += do_quad<QW, LAST, OFF, LAYER>(tid + 128, sin_, pin, sout, pout, gout, ecb, ty0, tx0);
        }
    }
    return s;
}

__global__ void __launch_bounds__(128, 6) flow_main(const float* __restrict__ x,
                                                    float* __restrict__ out) {
    const int tid = threadIdx.x;
    const int b = blockIdx.x;        // batch-major: consecutive blocks share tile -> ecb reuse
    const int tile = blockIdx.y;     // 0..31 : 4 x-tiles * 8 y-tiles
    const int tx0 = (tile & 3) * 32;
    const int ty0 = (tile >> 2) * 16;

    __shared__ __align__(16) float sA[3 * 22 * 40];
    __shared__ __align__(16) float sB[3 * 20 * 40];
    __shared__ float sred[128];

    // Load raw input tile (22 rows x 38 cols, wrap halo of 3)
    const float* __restrict__ xb = x + (size_t)b * (C * NIMG * NIMG);
    for (int i = tid; i < 3 * 22 * 38; i += 128) {
        int c = i / (22 * 38);
        int rem = i - c * (22 * 38);
        int r = rem / 38;
        int col = rem - r * 38;
        int gy = (ty0 + r - 3) & 127;
        int gx = (tx0 + col - 3) & 127;
        sA[c * (22 * 40) + r * 40 + col] = xb[(c * NIMG + gy) * NIMG + gx];
    }
    __syncthreads();

    float lg2acc = 0.f;
    // stage0: overflow (52) -> high tids (warps 2-3)
    lg2acc += stage_p<20, 36, false, 2, 0, true >(sA, 22 * 40, sB, 20 * 40, nullptr, ty0, tx0, tid);
    __syncthreads();
    // stage1: overflow (25) -> low tids (warp 0)
    lg2acc += stage_p<18, 34, false, 1, 1, false>(sB, 20 * 40, sA, 18 * 40, nullptr, ty0, tx0, tid);
    __syncthreads();
    // stage2: exact fit
    lg2acc += stage_p<16, 32, true, 0, 2, false>(sA, 18 * 40, nullptr, 0,
                                                 out + (size_t)b * (C * NIMG * NIMG), ty0, tx0, tid);

    sred[tid] = lg2acc;
    __syncthreads();
    for (int s = 64; s > 0; s >>= 1) {
        if (tid < s) sred[tid] += sred[tid + s];
        __syncthreads();
    }
    if (tid == 0) g_scratch[b * TILES + tile] = -LN2F * sred[0];
}

// =========================================================================
// F: per-batch logdet = scalar part + 32 tile partials (deterministic)
// =========================================================================
__global__ void final_ld(const float* __restrict__ als, float* __restrict__ out) {
    __shared__ float sred[256];
    int tid = threadIdx.x;
    float loc = 0.f;
    for (int i = tid; i < 576; i += 256) loc += g_cls_part[i];
    for (int i = tid; i < LNUM * 64; i += 256) loc += g_kld_part[i];
    sred[tid] = loc;
    __syncthreads();
    for (int s = 128; s > 0; s >>= 1) {
        if (tid < s) sred[tid] += sred[tid + s];
        __syncthreads();
    }
    if (tid == 0) {
        float s2 = 0.f;
        for (int i = 0; i < 9; i++) s2 += als[i];
        sred[0] = sred[0] + 16384.0f * s2;
    }
    __syncthreads();
    float scal = sred[0];
    int b = blockIdx.x * 256 + tid;
    if (b < BATCH) {
        float s = scal;
        #pragma unroll
        for (int t = 0; t < TILES; t++) s += g_scratch[b * TILES + t];
        out[H_ELEMS + b] = s;
    }
}

// =========================================================================
extern "C" void kernel_launch(void* const* d_in, const int* in_sizes, int n_in,
                              void* d_out, int out_size) {
    const float* x     = (const float*)d_in[0];
    const float* ab    = (const float*)d_in[1];
    const float* als   = (const float*)d_in[2];
    const float* K     = (const float*)d_in[3];
    const float* cbias = (const float*)d_in[4];
    const float* cls   = (const float*)d_in[5];
    const float* sla   = (const float*)d_in[6];
    float* out = (float*)d_out;

    prep_ecb<<<576, 256>>>(cls, cbias);
    prep_w<<<1, 256>>>(K, als, ab, sla);
    kld_kernel<<<64, 256>>>(K);

    // Device->constant-bank copies (graph-capturable D2D memcpy nodes).
    void* wsrc = nullptr;
    cudaGetSymbolAddress(&wsrc, g_Wpk);
    cudaMemcpyToSymbolAsync(c_W, wsrc, sizeof(ull) * LNUM * 90, 0,
                            cudaMemcpyDeviceToDevice, 0);
    void* asrc = nullptr;
    cudaGetSymbolAddress(&asrc, g_aux);
    cudaMemcpyToSymbolAsync(c_aux, asrc, sizeof(float) * LNUM * 12, 0,
                            cudaMemcpyDeviceToDevice, 0);

    flow_main<<<dim3(BATCH, TILES), 128>>>(x, out);   // 4th kernel (ncu target)
    final_ld<<<2, 256>>>(als, out);
}

// round 14
// speedup vs baseline: 1.5293x; 1.0055x over previous
#include <cuda_runtime.h>
#include <math.h>
#include <stdint.h>

typedef unsigned long long ull;

// Problem constants
#define BATCH 512
#define C 3
#define NIMG 128
#define LNUM 3
#define H_ELEMS (BATCH * C * NIMG * NIMG)   // 25165824
#define TILES 16                            // 4 x-tiles x 4 y-tiles of 32x32
#define LN2F 0.69314718055994531f

// ---------------- device scratch (no allocations allowed) ----------------
__device__ __align__(16) float g_ecb[LNUM * C * NIMG * NIMG * 2]; // {exp(cls), bias} dense 16B/px
__device__ __align__(16) ull   g_Wpk[LNUM * 90];   // packed dup weights [l][(in*3+o)*10+tap]
__device__ __align__(16) float g_aux[LNUM * 12];   // B[3], alpha[3], ln2/alpha[3], pad
__device__ float g_cls_part[576];
__device__ float g_kld_part[LNUM * 64];
__device__ float g_scratch[BATCH * TILES];

// Constant bank: weight pairs + per-layer aux (uniform/const path, no L1TEX)
__constant__ ull   c_W[LNUM * 90];
__constant__ float c_aux[LNUM * 12];

// ---------------- packed f32x2 helpers ----------------
__device__ __forceinline__ ull pk(float lo, float hi) {
    ull r; asm("mov.b64 %0,{%1,%2};" : "=l"(r) : "f"(lo), "f"(hi)); return r;
}
__device__ __forceinline__ void upk(ull p, float& lo, float& hi) {
    asm("mov.b64 {%0,%1},%2;" : "=f"(lo), "=f"(hi) : "l"(p));
}
__device__ __forceinline__ ull f2fma(ull a, ull b, ull c) {
    ull d; asm("fma.rn.f32x2 %0,%1,%2,%3;" : "=l"(d) : "l"(a), "l"(b), "l"(c)); return d;
}
// middle pair {hi(a), lo(b)}
__device__ __forceinline__ ull mkmid(ull a, ull b) {
    float alo, ahi, blo, bhi;
    asm("mov.b64 {%0,%1},%2;" : "=f"(alo), "=f"(ahi) : "l"(a));
    asm("mov.b64 {%0,%1},%2;" : "=f"(blo), "=f"(bhi) : "l"(b));
    ull m; asm("mov.b64 %0,{%1,%2};" : "=l"(m) : "f"(ahi), "f"(blo));
    return m;
}

// =========================================================================
// P1: exp(conv_log_scale) interleaved with conv_bias + partial sums of cls
// =========================================================================
__global__ void prep_ecb(const float* __restrict__ cls, const float* __restrict__ cbias) {
    __shared__ float sred[256];
    int idx = blockIdx.x * 256 + threadIdx.x;   // 576*256 = 147456 exactly
    float v = cls[idx];
    g_ecb[2 * idx]     = expf(v);
    g_ecb[2 * idx + 1] = cbias[idx];
    sred[threadIdx.x] = v;
    __syncthreads();
    for (int s = 128; s > 0; s >>= 1) {
        if (threadIdx.x < s) sred[threadIdx.x] += sred[threadIdx.x + s];
        __syncthreads();
    }
    if (threadIdx.x == 0) g_cls_part[blockIdx.x] = sred[0];
}

// =========================================================================
// P2: fold actnorm into conv weights (packed dup ull), alpha tables
// =========================================================================
__global__ void prep_w(const float* __restrict__ K, const float* __restrict__ als,
                       const float* __restrict__ ab, const float* __restrict__ sla) {
    int t = threadIdx.x;
    for (int i = t; i < LNUM * 90; i += 256) {
        int l = i / 90, r = i % 90;
        int in = r / 30, r2 = r % 30;
        int o = r2 / 10, tap = r2 % 10;
        float val = 0.f;
        if (tap < 9) {
            float a = expf(als[l * 3 + in]);
            val = K[((l * 3 + o) * 3 + in) * 9 + tap] * a;
        }
        g_Wpk[i] = pk(val, val);
    }
    for (int i = t; i < LNUM * 12; i += 256) {
        int l = i / 12, j = i % 12;
        float val = 0.f;
        if (j < 3) {
            float s = 0.f;
            for (int in = 0; in < 3; in++) {
                float ks = 0.f;
                for (int tap = 0; tap < 9; tap++)
                    ks += K[((l * 3 + j) * 3 + in) * 9 + tap];
                s += ab[l * 3 + in] * ks;
            }
            val = s;
        } else if (j < 6) {
            val = expf(sla[l * 3 + (j - 3)]);
        } else if (j < 9) {
            val = LN2F / expf(sla[l * 3 + (j - 6)]);   // ln2/alpha
        }
        g_aux[i] = val;
    }
}

// =========================================================================
// P3: spectral log|det| of circular conv operator
// =========================================================================
__global__ void kld_kernel(const float* __restrict__ K) {
    __shared__ float2 tw[128];
    __shared__ float sK[LNUM * 81];
    __shared__ float sred[256];
    int tid = threadIdx.x;
    if (tid < 128) {
        double a = -2.0 * 3.14159265358979323846 * (double)tid / 128.0;
        double s, c; sincos(a, &s, &c);
        tw[tid] = make_float2((float)c, (float)s);
    }
    if (tid < LNUM * 81) sK[tid] = K[tid];
    __syncthreads();

    int point = blockIdx.x * 256 + tid;  // 64*256 = 16384
    int u = point >> 7, v = point & 127;

    float res[LNUM];
    #pragma unroll
    for (int l = 0; l < LNUM; l++) {
        float er[9], ei[9];
        #pragma unroll
        for (int p = 0; p < 3; p++)
            #pragma unroll
            for (int q = 0; q < 3; q++) {
                int m = (u * p + v * q) & 127;
                float2 t = tw[m];
                er[p * 3 + q] = t.x; ei[p * 3 + q] = t.y;
            }
        float mr[3][3], mi[3][3];
        #pragma unroll
        for (int a = 0; a < 3; a++)
            #pragma unroll
            for (int b = 0; b < 3; b++) {
                float rr = 0.f, ri = 0.f;
                #pragma unroll
                for (int t = 0; t < 9; t++) {
                    float kk = sK[l * 81 + (a * 3 + b) * 9 + t];
                    rr += kk * er[t]; ri += kk * ei[t];
                }
                mr[a][b] = rr; mi[a][b] = ri;
            }
        float c0r = (mr[1][1]*mr[2][2] - mi[1][1]*mi[2][2]) - (mr[1][2]*mr[2][1] - mi[1][2]*mi[2][1]);
        float c0i = (mr[1][1]*mi[2][2] + mi[1][1]*mr[2][2]) - (mr[1][2]*mi[2][1] + mi[1][2]*mr[2][1]);
        float c1r = (mr[1][0]*mr[2][2] - mi[1][0]*mi[2][2]) - (mr[1][2]*mr[2][0] - mi[1][2]*mi[2][0]);
        float c1i = (mr[1][0]*mi[2][2] + mi[1][0]*mr[2][2]) - (mr[1][2]*mi[2][0] + mi[1][2]*mr[2][0]);
        float c2r = (mr[1][0]*mr[2][1] - mi[1][0]*mi[2][1]) - (mr[1][1]*mr[2][0] - mi[1][1]*mi[2][0]);
        float c2i = (mr[1][0]*mi[2][1] + mi[1][0]*mr[2][1]) - (mr[1][1]*mi[2][0] + mi[1][1]*mr[2][0]);
        float dr = (mr[0][0]*c0r - mi[0][0]*c0i) - (mr[0][1]*c1r - mi[0][1]*c1i) + (mr[0][2]*c2r - mi[0][2]*c2i);
        float di = (mr[0][0]*c0i + mi[0][0]*c0r) - (mr[0][1]*c1i + mi[0][1]*c1r) + (mr[0][2]*c2i + mi[0][2]*c2r);
        res[l] = 0.5f * logf(dr * dr + di * di);
    }

    for (int l = 0; l < LNUM; l++) {
        sred[tid] = res[l];
        __syncthreads();
        for (int s = 128; s > 0; s >>= 1) {
            if (tid < s) sred[tid] += sred[tid + s];
            __syncthreads();
        }
        if (tid == 0) g_kld_part[l * 64 + blockIdx.x] = sred[0];
        __syncthreads();
    }
}

// =========================================================================
// One 2x2 quad of one stage (32x32 tile). Weights + aux from constant bank.
// =========================================================================
template <int QW, bool LAST, int OFF, int LAYER>
__device__ __forceinline__ float do_quad(int q,
                                         const float* __restrict__ sin_, int pin,
                                         float* __restrict__ sout, int pout,
                                         float* __restrict__ gout,
                                         const float* __restrict__ ecb,
                                         int ty0, int tx0) {
    int qy = q / QW, qx = q - qy * QW;
    int py = qy * 2, px = qx * 2;

    ull acc2[2][3];
    #pragma unroll
    for (int o = 0; o < 3; o++) {
        float B = c_aux[LAYER * 12 + o];
        acc2[0][o] = pk(B, B);
        acc2[1][o] = acc2[0][o];
    }

    #pragma unroll
    for (int in = 0; in < 3; in++) {
        const float* bp = sin_ + in * pin + py * 40 + px;
        ull A[4], Bv[4], M[4];
        #pragma unroll
        for (int r = 0; r < 4; r++) {
            A[r]  = *(const ull*)(bp + r * 40);
            Bv[r] = *(const ull*)(bp + r * 40 + 2);
            M[r]  = mkmid(A[r], Bv[r]);
        }
        #pragma unroll
        for (int o = 0; o < 3; o++) {
            #pragma unroll
            for (int ty = 0; ty < 3; ty++) {
                ull w0 = c_W[LAYER * 90 + (in * 3 + o) * 10 + ty * 3 + 0];
                ull w1 = c_W[LAYER * 90 + (in * 3 + o) * 10 + ty * 3 + 1];
                ull w2 = c_W[LAYER * 90 + (in * 3 + o) * 10 + ty * 3 + 2];
                acc2[0][o] = f2fma(w0, A[ty],      acc2[0][o]);
                acc2[0][o] = f2fma(w1, M[ty],      acc2[0][o]);
                acc2[0][o] = f2fma(w2, Bv[ty],     acc2[0][o]);
                acc2[1][o] = f2fma(w0, A[ty + 1],  acc2[1][o]);
                acc2[1][o] = f2fma(w1, M[ty + 1],  acc2[1][o]);
                acc2[1][o] = f2fma(w2, Bv[ty + 1], acc2[1][o]);
            }
        }
    }

    // ---- epilogue (dense table, scattered float2 loads) ----
    int xl0 = px - OFF, yl0 = py - OFF;
    int gy0 = (ty0 + yl0) & 127;
    int gy1 = (ty0 + yl0 + 1) & 127;
    int gx0 = (tx0 + xl0) & 127;
    int gx1 = (tx0 + xl0 + 1) & 127;

    float lg2sum = 0.f;
    #pragma unroll
    for (int R = 0; R < 2; R++) {
        int yloc = py + R - OFF;
        int gy = R ? gy1 : gy0;
        #pragma unroll
        for (int o = 0; o < 3; o++) {
            float al   = c_aux[LAYER * 12 + 3 + o];
            float ial2 = c_aux[LAYER * 12 + 6 + o];
            float c0, c1; upk(acc2[R][o], c0, c1);
            float2 e0 = *(const float2*)&ecb[((o * NIMG + gy) * NIMG + gx0) * 2];
            float2 e1 = *(const float2*)&ecb[((o * NIMG + gy) * NIMG + gx1) * 2];
            float u0 = fmaf(e0.x, c0, e0.y);
            float u1 = fmaf(e1.x, c1, e1.y);
            float g0 = __log2f(fmaf(al, fabsf(u0), 1.0f));   // lg2(1 + a|u|)
            float g1 = __log2f(fmaf(al, fabsf(u1), 1.0f));
            float h0 = copysignf(ial2 * g0, u0);             // (ln2/a)*lg2 = log1p/a
            float h1 = copysignf(ial2 * g1, u1);
            if (LAST || ((unsigned)yloc < 32u && (unsigned)xl0 < 32u))       lg2sum += g0;
            if (LAST || ((unsigned)yloc < 32u && (unsigned)(xl0 + 1) < 32u)) lg2sum += g1;
            if (!LAST) {
                *(ull*)&sout[o * pout + (py + R) * 40 + px] = pk(h0, h1);
            } else {
                *(float2*)(gout + ((size_t)o * NIMG + gy) * NIMG + (tx0 + px)) =
                    make_float2(h0, h1);
            }
        }
    }
    return lg2sum;
}

// =========================================================================
// One stage (256 threads). Overflow quads rotated across warps per stage
// (HIGH_OVF: high tids / warps 5-7; else low tids / warps 0-1).
// =========================================================================
template <int D, bool LAST, int OFF, int LAYER, bool HIGH_OVF>
__device__ __forceinline__ float stage_p(const float* __restrict__ sin_, int pin,
                                         float* __restrict__ sout, int pout,
                                         float* __restrict__ gout,
                                         int ty0, int tx0, int tid) {
    const float* __restrict__ ecb = g_ecb + LAYER * (C * NIMG * NIMG * 2);
    constexpr int QH = D / 2;
    constexpr int QW = D / 2;
    constexpr int NQ = QH * QW;   // 324 / 289 / 256

    float s = do_quad<QW, LAST, OFF, LAYER>(tid, sin_, pin, sout, pout, gout, ecb, ty0, tx0);
    if constexpr (NQ > 256) {
        constexpr int V = NQ - 256;
        if constexpr (HIGH_OVF) {
            if (tid >= 256 - V)
                s += do_quad<QW, LAST, OFF, LAYER>(tid + V, sin_, pin, sout, pout, gout, ecb, ty0, tx0);
        } else {
            if (tid < V)
                s += do_quad<QW, LAST, OFF, LAYER>(tid + 256, sin_, pin, sout, pout, gout, ecb, ty0, tx0);
        }
    }
    return s;
}

__global__ void __launch_bounds__(256, 3) flow_main(const float* __restrict__ x,
                                                    float* __restrict__ out) {
    const int tid = threadIdx.x;
    const int b = blockIdx.x;        // batch-major: consecutive blocks share tile -> ecb reuse
    const int tile = blockIdx.y;     // 0..15 : 4 x-tiles * 4 y-tiles of 32x32
    const int tx0 = (tile & 3) * 32;
    const int ty0 = (tile >> 2) * 32;

    __shared__ __align__(16) float sA[3 * 38 * 40];   // 18240 B
    __shared__ __align__(16) float sB[3 * 36 * 40];   // 17280 B
    __shared__ float sred[256];

    // Load raw input tile (38 rows x 38 cols, wrap halo of 3)
    const float* __restrict__ xb = x + (size_t)b * (C * NIMG * NIMG);
    for (int i = tid; i < 3 * 38 * 38; i += 256) {
        int c = i / (38 * 38);
        int rem = i - c * (38 * 38);
        int r = rem / 38;
        int col = rem - r * 38;
        int gy = (ty0 + r - 3) & 127;
        int gx = (tx0 + col - 3) & 127;
        sA[c * (38 * 40) + r * 40 + col] = xb[(c * NIMG + gy) * NIMG + gx];
    }
    __syncthreads();

    float lg2acc = 0.f;
    // stage0: 18x18=324 quads, overflow 68 -> high tids (warps ~5-7)
    lg2acc += stage_p<36, false, 2, 0, true >(sA, 38 * 40, sB, 36 * 40, nullptr, ty0, tx0, tid);
    __syncthreads();
    // stage1: 17x17=289 quads, overflow 33 -> low tids (warps 0-1)
    lg2acc += stage_p<34, false, 1, 1, false>(sB, 36 * 40, sA, 34 * 40, nullptr, ty0, tx0, tid);
    __syncthreads();
    // stage2: 16x16=256 exact
    lg2acc += stage_p<32, true, 0, 2, false>(sA, 34 * 40, nullptr, 0,
                                             out + (size_t)b * (C * NIMG * NIMG), ty0, tx0, tid);

    sred[tid] = lg2acc;
    __syncthreads();
    for (int s = 128; s > 0; s >>= 1) {
        if (tid < s) sred[tid] += sred[tid + s];
        __syncthreads();
    }
    if (tid == 0) g_scratch[b * TILES + tile] = -LN2F * sred[0];
}

// =========================================================================
// F: per-batch logdet = scalar part + 16 tile partials (deterministic)
// =========================================================================
__global__ void final_ld(const float* __restrict__ als, float* __restrict__ out) {
    __shared__ float sred[256];
    int tid = threadIdx.x;
    float loc = 0.f;
    for (int i = tid; i < 576; i += 256) loc += g_cls_part[i];
    for (int i = tid; i < LNUM * 64; i += 256) loc += g_kld_part[i];
    sred[tid] = loc;
    __syncthreads();
    for (int s = 128; s > 0; s >>= 1) {
        if (tid < s) sred[tid] += sred[tid + s];
        __syncthreads();
    }
    if (tid == 0) {
        float s2 = 0.f;
        for (int i = 0; i < 9; i++) s2 += als[i];
        sred[0] = sred[0] + 16384.0f * s2;
    }
    __syncthreads();
    float scal = sred[0];
    int b = blockIdx.x * 256 + tid;
    if (b < BATCH) {
        float s = scal;
        #pragma unroll
        for (int t = 0; t < TILES; t++) s += g_scratch[b * TILES + t];
        out[H_ELEMS + b] = s;
    }
}

// =========================================================================
extern "C" void kernel_launch(void* const* d_in, const int* in_sizes, int n_in,
                              void* d_out, int out_size) {
    const float* x     = (const float*)d_in[0];
    const float* ab    = (const float*)d_in[1];
    const float* als   = (const float*)d_in[2];
    const float* K     = (const float*)d_in[3];
    const float* cbias = (const float*)d_in[4];
    const float* cls   = (const float*)d_in[5];
    const float* sla   = (const float*)d_in[6];
    float* out = (float*)d_out;

    prep_ecb<<<576, 256>>>(cls, cbias);
    prep_w<<<1, 256>>>(K, als, ab, sla);
    kld_kernel<<<64, 256>>>(K);

    // Device->constant-bank copies (graph-capturable D2D memcpy nodes).
    void* wsrc = nullptr;
    cudaGetSymbolAddress(&wsrc, g_Wpk);
    cudaMemcpyToSymbolAsync(c_W, wsrc, sizeof(ull) * LNUM * 90, 0,
                            cudaMemcpyDeviceToDevice, 0);
    void* asrc = nullptr;
    cudaGetSymbolAddress(&asrc, g_aux);
    cudaMemcpyToSymbolAsync(c_aux, asrc, sizeof(float) * LNUM * 12, 0,
                            cudaMemcpyDeviceToDevice, 0);

    flow_main<<<dim3(BATCH, TILES), 256>>>(x, out);   // 4th kernel (ncu target)
    final_ld<<<2, 256>>>(als, out);
}

// round 15
// speedup vs baseline: 2.1426x; 1.4010x over previous
#include <cuda_runtime.h>
#include <math.h>
#include <stdint.h>

typedef unsigned long long ull;

// Problem constants
#define BATCH 512
#define C 3
#define NIMG 128
#define LNUM 3
#define H_ELEMS (BATCH * C * NIMG * NIMG)   // 25165824
#define TILES 16                            // 4 x-tiles x 4 y-tiles of 32x32
#define LN2F 0.69314718055994531f

// Padded ecb table geometry: rows/cols shifted +2, wrap-replicated edges.
#define EP_ROWS 133
#define EP_COLS 134
#define EP_PLANE (EP_ROWS * EP_COLS)        // per (l,o) plane, in float2 units
#define EP_TOTAL (LNUM * C * EP_PLANE)      // 160398 entries
#define ECB_BLKS 627                        // 627*256 = 160512 >= 160398

// ---------------- device scratch (no allocations allowed) ----------------
__device__ __align__(16) float g_ecbP[EP_TOTAL * 2];  // {exp(cls), bias} pre-wrapped
__device__ __align__(16) ull   g_Wpk[LNUM * 90];      // packed dup weights
__device__ __align__(16) float g_aux[LNUM * 12];      // B[3], alpha[3], ln2/alpha[3]
__device__ float g_cls_part[ECB_BLKS];
__device__ float g_kld_part[LNUM * 64];
__device__ float g_scratch[BATCH * TILES];

// Constant bank: weight pairs + per-layer aux
__constant__ ull   c_W[LNUM * 90];
__constant__ float c_aux[LNUM * 12];

// ---------------- packed f32x2 helpers ----------------
__device__ __forceinline__ ull pk(float lo, float hi) {
    ull r; asm("mov.b64 %0,{%1,%2};" : "=l"(r) : "f"(lo), "f"(hi)); return r;
}
__device__ __forceinline__ void upk(ull p, float& lo, float& hi) {
    asm("mov.b64 {%0,%1},%2;" : "=f"(lo), "=f"(hi) : "l"(p));
}
__device__ __forceinline__ ull f2fma(ull a, ull b, ull c) {
    ull d; asm("fma.rn.f32x2 %0,%1,%2,%3;" : "=l"(d) : "l"(a), "l"(b), "l"(c)); return d;
}
// middle pair {hi(a), lo(b)}
__device__ __forceinline__ ull mkmid(ull a, ull b) {
    float alo, ahi, blo, bhi;
    asm("mov.b64 {%0,%1},%2;" : "=f"(alo), "=f"(ahi) : "l"(a));
    asm("mov.b64 {%0,%1},%2;" : "=f"(blo), "=f"(bhi) : "l"(b));
    ull m; asm("mov.b64 %0,{%1,%2};" : "=l"(m) : "f"(ahi), "f"(blo));
    return m;
}

// =========================================================================
// P1: build pre-wrapped padded {exp(cls), bias} table + partial cls sums.
// Table index = ((lo)*EP_ROWS + row)*EP_COLS + col, (row,col) shifted +2.
// =========================================================================
__global__ void prep_ecb(const float* __restrict__ cls, const float* __restrict__ cbias) {
    __shared__ float sred[256];
    int idx = blockIdx.x * 256 + threadIdx.x;
    if (idx < EP_TOTAL) {
        int col = idx % EP_COLS;
        int r2  = idx / EP_COLS;
        int row = r2 % EP_ROWS;
        int lo  = r2 / EP_ROWS;               // 0..8 = l*3+o
        int gx = (col - 2) & 127;
        int gy = (row - 2) & 127;
        int src = (lo * 128 + gy) * 128 + gx;
        g_ecbP[2 * idx]     = expf(cls[src]);
        g_ecbP[2 * idx + 1] = cbias[src];
    }
    float v = 0.f;
    if (idx < LNUM * C * NIMG * NIMG) v = cls[idx];
    sred[threadIdx.x] = v;
    __syncthreads();
    for (int s = 128; s > 0; s >>= 1) {
        if (threadIdx.x < s) sred[threadIdx.x] += sred[threadIdx.x + s];
        __syncthreads();
    }
    if (threadIdx.x == 0) g_cls_part[blockIdx.x] = sred[0];
}

// =========================================================================
// P2: fold actnorm into conv weights (packed dup ull), alpha tables
// =========================================================================
__global__ void prep_w(const float* __restrict__ K, const float* __restrict__ als,
                       const float* __restrict__ ab, const float* __restrict__ sla) {
    int t = threadIdx.x;
    for (int i = t; i < LNUM * 90; i += 256) {
        int l = i / 90, r = i % 90;
        int in = r / 30, r2 = r % 30;
        int o = r2 / 10, tap = r2 % 10;
        float val = 0.f;
        if (tap < 9) {
            float a = expf(als[l * 3 + in]);
            val = K[((l * 3 + o) * 3 + in) * 9 + tap] * a;
        }
        g_Wpk[i] = pk(val, val);
    }
    for (int i = t; i < LNUM * 12; i += 256) {
        int l = i / 12, j = i % 12;
        float val = 0.f;
        if (j < 3) {
            float s = 0.f;
            for (int in = 0; in < 3; in++) {
                float ks = 0.f;
                for (int tap = 0; tap < 9; tap++)
                    ks += K[((l * 3 + j) * 3 + in) * 9 + tap];
                s += ab[l * 3 + in] * ks;
            }
            val = s;
        } else if (j < 6) {
            val = expf(sla[l * 3 + (j - 3)]);
        } else if (j < 9) {
            val = LN2F / expf(sla[l * 3 + (j - 6)]);   // ln2/alpha
        }
        g_aux[i] = val;
    }
}

// =========================================================================
// P3: spectral log|det| of circular conv operator
// =========================================================================
__global__ void kld_kernel(const float* __restrict__ K) {
    __shared__ float2 tw[128];
    __shared__ float sK[LNUM * 81];
    __shared__ float sred[256];
    int tid = threadIdx.x;
    if (tid < 128) {
        double a = -2.0 * 3.14159265358979323846 * (double)tid / 128.0;
        double s, c; sincos(a, &s, &c);
        tw[tid] = make_float2((float)c, (float)s);
    }
    if (tid < LNUM * 81) sK[tid] = K[tid];
    __syncthreads();

    int point = blockIdx.x * 256 + tid;  // 64*256 = 16384
    int u = point >> 7, v = point & 127;

    float res[LNUM];
    #pragma unroll
    for (int l = 0; l < LNUM; l++) {
        float er[9], ei[9];
        #pragma unroll
        for (int p = 0; p < 3; p++)
            #pragma unroll
            for (int q = 0; q < 3; q++) {
                int m = (u * p + v * q) & 127;
                float2 t = tw[m];
                er[p * 3 + q] = t.x; ei[p * 3 + q] = t.y;
            }
        float mr[3][3], mi[3][3];
        #pragma unroll
        for (int a = 0; a < 3; a++)
            #pragma unroll
            for (int b = 0; b < 3; b++) {
                float rr = 0.f, ri = 0.f;
                #pragma unroll
                for (int t = 0; t < 9; t++) {
                    float kk = sK[l * 81 + (a * 3 + b) * 9 + t];
                    rr += kk * er[t]; ri += kk * ei[t];
                }
                mr[a][b] = rr; mi[a][b] = ri;
            }
        float c0r = (mr[1][1]*mr[2][2] - mi[1][1]*mi[2][2]) - (mr[1][2]*mr[2][1] - mi[1][2]*mi[2][1]);
        float c0i = (mr[1][1]*mi[2][2] + mi[1][1]*mr[2][2]) - (mr[1][2]*mi[2][1] + mi[1][2]*mr[2][1]);
        float c1r = (mr[1][0]*mr[2][2] - mi[1][0]*mi[2][2]) - (mr[1][2]*mr[2][0] - mi[1][2]*mi[2][0]);
        float c1i = (mr[1][0]*mi[2][2] + mi[1][0]*mr[2][2]) - (mr[1][2]*mi[2][0] + mi[1][2]*mr[2][0]);
        float c2r = (mr[1][0]*mr[2][1] - mi[1][0]*mi[2][1]) - (mr[1][1]*mr[2][0] - mi[1][1]*mi[2][0]);
        float c2i = (mr[1][0]*mi[2][1] + mi[1][0]*mr[2][1]) - (mr[1][1]*mi[2][0] + mi[1][1]*mr[2][0]);
        float dr = (mr[0][0]*c0r - mi[0][0]*c0i) - (mr[0][1]*c1r - mi[0][1]*c1i) + (mr[0][2]*c2r - mi[0][2]*c2i);
        float di = (mr[0][0]*c0i + mi[0][0]*c0r) - (mr[0][1]*c1i + mi[0][1]*c1r) + (mr[0][2]*c2i + mi[0][2]*c2r);
        res[l] = 0.5f * logf(dr * dr + di * di);
    }

    for (int l = 0; l < LNUM; l++) {
        sred[tid] = res[l];
        __syncthreads();
        for (int s = 128; s > 0; s >>= 1) {
            if (tid < s) sred[tid] += sred[tid + s];
            __syncthreads();
        }
        if (tid == 0) g_kld_part[l * 64 + blockIdx.x] = sred[0];
        __syncthreads();
    }
}

// =========================================================================
// One 2x2 quad of one stage (32x32 tile). Weights + aux from constant bank.
// Epilogue: single base address into pre-wrapped table, immediate offsets.
// =========================================================================
template <int QW, bool LAST, int OFF, int LAYER>
__device__ __forceinline__ float do_quad(int q,
                                         const float* __restrict__ sin_, int pin,
                                         float* __restrict__ sout, int pout,
                                         float* __restrict__ gout,
                                         const float2* __restrict__ ecbP,
                                         int ty0, int tx0) {
    int qy = q / QW, qx = q - qy * QW;
    int py = qy * 2, px = qx * 2;

    ull acc2[2][3];
    #pragma unroll
    for (int o = 0; o < 3; o++) {
        float B = c_aux[LAYER * 12 + o];
        acc2[0][o] = pk(B, B);
        acc2[1][o] = acc2[0][o];
    }

    #pragma unroll
    for (int in = 0; in < 3; in++) {
        const float* bp = sin_ + in * pin + py * 40 + px;
        ull A[4], Bv[4], M[4];
        #pragma unroll
        for (int r = 0; r < 4; r++) {
            A[r]  = *(const ull*)(bp + r * 40);
            Bv[r] = *(const ull*)(bp + r * 40 + 2);
            M[r]  = mkmid(A[r], Bv[r]);
        }
        #pragma unroll
        for (int o = 0; o < 3; o++) {
            #pragma unroll
            for (int ty = 0; ty < 3; ty++) {
                ull w0 = c_W[LAYER * 90 + (in * 3 + o) * 10 + ty * 3 + 0];
                ull w1 = c_W[LAYER * 90 + (in * 3 + o) * 10 + ty * 3 + 1];
                ull w2 = c_W[LAYER * 90 + (in * 3 + o) * 10 + ty * 3 + 2];
                acc2[0][o] = f2fma(w0, A[ty],      acc2[0][o]);
                acc2[0][o] = f2fma(w1, M[ty],      acc2[0][o]);
                acc2[0][o] = f2fma(w2, Bv[ty],     acc2[0][o]);
                acc2[1][o] = f2fma(w0, A[ty + 1],  acc2[1][o]);
                acc2[1][o] = f2fma(w1, M[ty + 1],  acc2[1][o]);
                acc2[1][o] = f2fma(w2, Bv[ty + 1], acc2[1][o]);
            }
        }
    }

    // ---- epilogue: ONE address, all 12 float2 loads at immediate offsets ----
    int xl0 = px - OFF, yl0 = py - OFF;
    const float2* ep0 = ecbP + (ty0 + yl0 + 2) * EP_COLS + (tx0 + xl0 + 2);

    float lg2sum = 0.f;
    #pragma unroll
    for (int R = 0; R < 2; R++) {
        int yloc = py + R - OFF;
        #pragma unroll
        for (int o = 0; o < 3; o++) {
            float al   = c_aux[LAYER * 12 + 3 + o];
            float ial2 = c_aux[LAYER * 12 + 6 + o];
            float c0, c1; upk(acc2[R][o], c0, c1);
            const float2* p = ep0 + o * EP_PLANE + R * EP_COLS;
            float2 e0 = p[0];
            float2 e1 = p[1];
            float u0 = fmaf(e0.x, c0, e0.y);
            float u1 = fmaf(e1.x, c1, e1.y);
            float g0 = __log2f(fmaf(al, fabsf(u0), 1.0f));   // lg2(1 + a|u|)
            float g1 = __log2f(fmaf(al, fabsf(u1), 1.0f));
            float h0 = copysignf(ial2 * g0, u0);             // (ln2/a)*lg2 = log1p/a
            float h1 = copysignf(ial2 * g1, u1);
            if (LAST || ((unsigned)yloc < 32u && (unsigned)xl0 < 32u))       lg2sum += g0;
            if (LAST || ((unsigned)yloc < 32u && (unsigned)(xl0 + 1) < 32u)) lg2sum += g1;
            if (!LAST) {
                *(ull*)&sout[o * pout + (py + R) * 40 + px] = pk(h0, h1);
            } else {
                // OFF==0: gy = ty0+py+R, never wraps
                *(float2*)(gout + ((size_t)o * NIMG + (ty0 + py + R)) * NIMG + (tx0 + px)) =
                    make_float2(h0, h1);
            }
        }
    }
    return lg2sum;
}

// =========================================================================
// One stage (256 threads). Overflow quads rotated across warps per stage.
// =========================================================================
template <int D, bool LAST, int OFF, int LAYER, bool HIGH_OVF>
__device__ __forceinline__ float stage_p(const float* __restrict__ sin_, int pin,
                                         float* __restrict__ sout, int pout,
                                         float* __restrict__ gout,
                                         int ty0, int tx0, int tid) {
    const float2* __restrict__ ecbP =
        (const float2*)g_ecbP + (size_t)LAYER * (C * EP_PLANE);
    constexpr int QH = D / 2;
    constexpr int QW = D / 2;
    constexpr int NQ = QH * QW;   // 324 / 289 / 256

    float s = do_quad<QW, LAST, OFF, LAYER>(tid, sin_, pin, sout, pout, gout, ecbP, ty0, tx0);
    if constexpr (NQ > 256) {
        constexpr int V = NQ - 256;
        if constexpr (HIGH_OVF) {
            if (tid >= 256 - V)
                s += do_quad<QW, LAST, OFF, LAYER>(tid + V, sin_, pin, sout, pout, gout, ecbP, ty0, tx0);
        } else {
            if (tid < V)
                s += do_quad<QW, LAST, OFF, LAYER>(tid + 256, sin_, pin, sout, pout, gout, ecbP, ty0, tx0);
        }
    }
    return s;
}

__global__ void __launch_bounds__(256, 3) flow_main(const float* __restrict__ x,
                                                    float* __restrict__ out) {
    const int tid = threadIdx.x;
    const int b = blockIdx.x;        // batch-major
    const int tile = blockIdx.y;     // 0..15 : 4 x-tiles * 4 y-tiles of 32x32
    const int tx0 = (tile & 3) * 32;
    const int ty0 = (tile >> 2) * 32;

    __shared__ __align__(16) float sA[3 * 38 * 40];
    __shared__ __align__(16) float sB[3 * 36 * 40];
    __shared__ float sred[256];

    // Vectorized loader: float4 LDG (wrap at float4-column granularity),
    // predicated scalar STS into local layout (local col 0 <-> gx tx0-3).
    const float4* __restrict__ xb4 =
        (const float4*)(x + (size_t)b * (C * NIMG * NIMG));
    const int gx4base = tx0 >> 2;
    for (int u = tid; u < 114 * 10; u += 256) {      // 114 rows (3ch x 38), 10 float4 each
        int row = u / 10, k = u - row * 10;
        int c = row / 38, r = row - c * 38;
        int gx4 = (gx4base - 1 + k) & 31;
        int gy  = (ty0 + r - 3) & 127;
        float4 v = xb4[((c << 7) + gy) * 32 + gx4];
        float* dst = sA + c * (38 * 40) + r * 40;
        int Lb = k * 4 - 1;
        if ((unsigned)(Lb + 0) < 38u) dst[Lb + 0] = v.x;
        if ((unsigned)(Lb + 1) < 38u) dst[Lb + 1] = v.y;
        if ((unsigned)(Lb + 2) < 38u) dst[Lb + 2] = v.z;
        if ((unsigned)(Lb + 3) < 38u) dst[Lb + 3] = v.w;
    }
    __syncthreads();

    float lg2acc = 0.f;
    // stage0: 18x18=324 quads, overflow 68 -> high tids
    lg2acc += stage_p<36, false, 2, 0, true >(sA, 38 * 40, sB, 36 * 40, nullptr, ty0, tx0, tid);
    __syncthreads();
    // stage1: 17x17=289 quads, overflow 33 -> low tids
    lg2acc += stage_p<34, false, 1, 1, false>(sB, 36 * 40, sA, 34 * 40, nullptr, ty0, tx0, tid);
    __syncthreads();
    // stage2: 16x16=256 exact
    lg2acc += stage_p<32, true, 0, 2, false>(sA, 34 * 40, nullptr, 0,
                                             out + (size_t)b * (C * NIMG * NIMG), ty0, tx0, tid);

    sred[tid] = lg2acc;
    __syncthreads();
    for (int s = 128; s > 0; s >>= 1) {
        if (tid < s) sred[tid] += sred[tid + s];
        __syncthreads();
    }
    if (tid == 0) g_scratch[b * TILES + tile] = -LN2F * sred[0];
}

// =========================================================================
// F: per-batch logdet = scalar part + 16 tile partials (deterministic)
// =========================================================================
__global__ void final_ld(const float* __restrict__ als, float* __restrict__ out) {
    __shared__ float sred[256];
    int tid = threadIdx.x;
    float loc = 0.f;
    for (int i = tid; i < ECB_BLKS; i += 256) loc += g_cls_part[i];
    for (int i = tid; i < LNUM * 64; i += 256) loc += g_kld_part[i];
    sred[tid] = loc;
    __syncthreads();
    for (int s = 128; s > 0; s >>= 1) {
        if (tid < s) sred[tid] += sred[tid + s];
        __syncthreads();
    }
    if (tid == 0) {
        float s2 = 0.f;
        for (int i = 0; i < 9; i++) s2 += als[i];
        sred[0] = sred[0] + 16384.0f * s2;
    }
    __syncthreads();
    float scal = sred[0];
    int b = blockIdx.x * 256 + tid;
    if (b < BATCH) {
        float s = scal;
        #pragma unroll
        for (int t = 0; t < TILES; t++) s += g_scratch[b * TILES + t];
        out[H_ELEMS + b] = s;
    }
}

// =========================================================================
extern "C" void kernel_launch(void* const* d_in, const int* in_sizes, int n_in,
                              void* d_out, int out_size) {
    const float* x     = (const float*)d_in[0];
    const float* ab    = (const float*)d_in[1];
    const float* als   = (const float*)d_in[2];
    const float* K     = (const float*)d_in[3];
    const float* cbias = (const float*)d_in[4];
    const float* cls   = (const float*)d_in[5];
    const float* sla   = (const float*)d_in[6];
    float* out = (float*)d_out;

    prep_ecb<<<ECB_BLKS, 256>>>(cls, cbias);
    prep_w<<<1, 256>>>(K, als, ab, sla);
    kld_kernel<<<64, 256>>>(K);

    // Device->constant-bank copies (graph-capturable D2D memcpy nodes).
    void* wsrc = nullptr;
    cudaGetSymbolAddress(&wsrc, g_Wpk);
    cudaMemcpyToSymbolAsync(c_W, wsrc, sizeof(ull) * LNUM * 90, 0,
                            cudaMemcpyDeviceToDevice, 0);
    void* asrc = nullptr;
    cudaGetSymbolAddress(&asrc, g_aux);
    cudaMemcpyToSymbolAsync(c_aux, asrc, sizeof(float) * LNUM * 12, 0,
                            cudaMemcpyDeviceToDevice, 0);

    flow_main<<<dim3(BATCH, TILES), 256>>>(x, out);   // 4th kernel (ncu target)
    final_ld<<<2, 256>>>(als, out);
}